// round 4
// baseline (speedup 1.0000x reference)
#include <cuda_runtime.h>
#include <cstdint>

// UniformShardedEmbeddingBags: B=1024, T=32, D=64, E=100000, L=50
// out[bag, :] = sum_{j<50} W[feat[bag*50 + j], bag % 32, :]
//
// One warp per bag, table-grouped bag order (R2: keeps duplicate rows of a
// table resident in L2 -> DRAM traffic at compulsory floor ~348MB).
// R3 (re-bench after infra failure): float4 gathers. Each LDG.128 fetches
// TWO rows: lanes 0-15 take draw k (float4 position lane&15), lanes 16-31
// take draw k+1. One per-lane-source shfl distributes both row indices.
// Halves LDG+SHFL count, doubles bytes-in-flight per warp. Output stored
// with __stcs (evict-first) so the 8MB of writes don't evict gather lines.

namespace {
constexpr int kT = 32;
constexpr int kD = 64;
constexpr int kL = 50;
constexpr int kNumBags = 1024 * kT;                  // 32768
constexpr int kThreads = 256;                        // 8 warps / block
constexpr int kBlocks = kNumBags / (kThreads / 32);  // 4096
constexpr int kRowF4 = kD / 4;                       // 16 float4 per row
constexpr size_t kEStrideF4 = (size_t)kT * kD / 4;   // 512 float4 per e
}  // namespace

__global__ __launch_bounds__(kThreads)
void embedding_bag_kernel(const float* __restrict__ weights,
                          const int* __restrict__ features,
                          float* __restrict__ out) {
    const int w = (blockIdx.x * kThreads + threadIdx.x) >> 5;
    const int lane = threadIdx.x & 31;

    // Table-grouped remap: warps [t*1024, (t+1)*1024) all pool table t.
    const int bag = ((w & 1023) << 5) | (w >> 10);
    const int table = w >> 10;  // == bag & 31

    const int* __restrict__ idxp = features + bag * kL;

    // Coalesced index fetch: lane j holds draw j; lanes 0..17 also draw 32+j.
    const int i0 = idxp[lane];
    const int i1 = (lane < kL - 32) ? idxp[32 + lane] : 0;

    const int half = lane >> 4;   // 0: even draw, 1: odd draw
    const int pos = lane & 15;    // float4 position within the row

    const float4* __restrict__ base =
        reinterpret_cast<const float4*>(weights) + (size_t)table * kRowF4;

    float4 acc0 = make_float4(0.f, 0.f, 0.f, 0.f);
    float4 acc1 = make_float4(0.f, 0.f, 0.f, 0.f);

    // Draws 0..31 (16 LDG.128, two rows each).
#pragma unroll
    for (int k = 0; k < 32; k += 4) {
        const int ea = __shfl_sync(0xffffffffu, i0, k + half);
        const int eb = __shfl_sync(0xffffffffu, i0, k + 2 + half);
        const float4 va = __ldg(base + (size_t)ea * kEStrideF4 + pos);
        const float4 vb = __ldg(base + (size_t)eb * kEStrideF4 + pos);
        acc0.x += va.x; acc0.y += va.y; acc0.z += va.z; acc0.w += va.w;
        acc1.x += vb.x; acc1.y += vb.y; acc1.z += vb.z; acc1.w += vb.w;
    }
    // Draws 32..47 (8 paired LDG.128), then draws 48/49 (1 LDG.128).
#pragma unroll
    for (int k = 0; k < 16; k += 4) {
        const int ea = __shfl_sync(0xffffffffu, i1, k + half);
        const int eb = __shfl_sync(0xffffffffu, i1, k + 2 + half);
        const float4 va = __ldg(base + (size_t)ea * kEStrideF4 + pos);
        const float4 vb = __ldg(base + (size_t)eb * kEStrideF4 + pos);
        acc0.x += va.x; acc0.y += va.y; acc0.z += va.z; acc0.w += va.w;
        acc1.x += vb.x; acc1.y += vb.y; acc1.z += vb.z; acc1.w += vb.w;
    }
    {
        const int ea = __shfl_sync(0xffffffffu, i1, 16 + half);  // draws 48,49
        const float4 va = __ldg(base + (size_t)ea * kEStrideF4 + pos);
        acc0.x += va.x; acc0.y += va.y; acc0.z += va.z; acc0.w += va.w;
    }

    // Merge odd/even draw accumulators, then fold the two half-warps so
    // lanes 0-15 hold the bag total at float4 position `pos`.
    float4 r;
    r.x = acc0.x + acc1.x;
    r.y = acc0.y + acc1.y;
    r.z = acc0.z + acc1.z;
    r.w = acc0.w + acc1.w;
    r.x += __shfl_xor_sync(0xffffffffu, r.x, 16);
    r.y += __shfl_xor_sync(0xffffffffu, r.y, 16);
    r.z += __shfl_xor_sync(0xffffffffu, r.z, 16);
    r.w += __shfl_xor_sync(0xffffffffu, r.w, 16);

    if (lane < 16) {
        __stcs(reinterpret_cast<float4*>(out) + (size_t)bag * kRowF4 + pos, r);
    }
}

extern "C" void kernel_launch(void* const* d_in, const int* in_sizes, int n_in,
                              void* d_out, int out_size) {
    const float* weights  = (const float*)d_in[0];   // (E, T, D) fp32
    const int*   features = (const int*)d_in[1];     // (B*T*L,) int32
    // d_in[2]: offsets — uniform arange*L, folded into compile-time constants.
    float* out = (float*)d_out;                      // (B, T, D) fp32

    embedding_bag_kernel<<<kBlocks, kThreads>>>(weights, features, out);
}

// round 5
// speedup vs baseline: 1.0458x; 1.0458x over previous
#include <cuda_runtime.h>
#include <cstdint>

// UniformShardedEmbeddingBags: B=1024, T=32, D=64, E=100000, L=50
// out[bag, :] = sum_{j<50} W[feat[bag*50 + j], bag % 32, :]
//
// R5 = revert to the proven R2 structure (float2 gathers, 32 regs, occ ~91%
// — R4 showed regs>32 costs occupancy and DRAM util) plus cache-policy
// hints only:
//   - indices read with __ldcs (streamed once, keep out of L2 ways)
//   - output written with __stcs (evict-first; 8MB of writes must not
//     displace the ~90MB resident gather working set)
// Table-grouped bag order keeps ~9 of 32 table slices L2-resident so all
// duplicate draws hit L2; DRAM traffic sits at the compulsory ~348MB floor.

namespace {
constexpr int kT = 32;
constexpr int kD = 64;
constexpr int kL = 50;
constexpr int kNumBags = 1024 * kT;                  // 32768
constexpr int kThreads = 256;                        // 8 warps / block
constexpr int kBlocks = kNumBags / (kThreads / 32);  // 4096
}  // namespace

__global__ __launch_bounds__(kThreads)
void embedding_bag_kernel(const float* __restrict__ weights,
                          const int* __restrict__ features,
                          float* __restrict__ out) {
    const int w = (blockIdx.x * kThreads + threadIdx.x) >> 5;
    const int lane = threadIdx.x & 31;

    // Table-grouped remap: warps [t*1024, (t+1)*1024) all pool table t.
    const int bag = ((w & 1023) << 5) | (w >> 10);
    const int table = w >> 10;  // == bag & 31

    const int* __restrict__ idxp = features + bag * kL;

    // Coalesced one-shot index fetch (streaming): lane j holds draw j,
    // lanes 0..17 also hold draw 32+j.
    const int i0 = __ldcs(idxp + lane);
    const int i1 = (lane < kL - 32) ? __ldcs(idxp + 32 + lane) : 0;

    // Base pointer into this bag's table slice, as float2.
    const float2* __restrict__ base =
        reinterpret_cast<const float2*>(weights) + (size_t)table * (kD / 2);
    constexpr size_t kRowStride2 = (size_t)kT * kD / 2;  // 1024 float2 per e

    float2 acc0 = make_float2(0.f, 0.f);
    float2 acc1 = make_float2(0.f, 0.f);

#pragma unroll
    for (int k = 0; k < 32; k += 2) {
        const int ia = __shfl_sync(0xffffffffu, i0, k);
        const int ib = __shfl_sync(0xffffffffu, i0, k + 1);
        const float2 va = __ldg(base + (size_t)ia * kRowStride2 + lane);
        const float2 vb = __ldg(base + (size_t)ib * kRowStride2 + lane);
        acc0.x += va.x; acc0.y += va.y;
        acc1.x += vb.x; acc1.y += vb.y;
    }
#pragma unroll
    for (int k = 0; k < 18; k += 2) {
        const int ia = __shfl_sync(0xffffffffu, i1, k);
        const int ib = __shfl_sync(0xffffffffu, i1, k + 1);
        const float2 va = __ldg(base + (size_t)ia * kRowStride2 + lane);
        const float2 vb = __ldg(base + (size_t)ib * kRowStride2 + lane);
        acc0.x += va.x; acc0.y += va.y;
        acc1.x += vb.x; acc1.y += vb.y;
    }

    float2 r;
    r.x = acc0.x + acc1.x;
    r.y = acc0.y + acc1.y;
    __stcs(reinterpret_cast<float2*>(out) + (size_t)bag * (kD / 2) + lane, r);
}

extern "C" void kernel_launch(void* const* d_in, const int* in_sizes, int n_in,
                              void* d_out, int out_size) {
    const float* weights  = (const float*)d_in[0];   // (E, T, D) fp32
    const int*   features = (const int*)d_in[1];     // (B*T*L,) int32
    // d_in[2]: offsets — uniform arange*L, folded into compile-time constants.
    float* out = (float*)d_out;                      // (B, T, D) fp32

    embedding_bag_kernel<<<kBlocks, kThreads>>>(weights, features, out);
}